// round 1
// baseline (speedup 1.0000x reference)
#include <cuda_runtime.h>

// GEMV: y = alpha * (A @ x) + beta * b
// A: [16384, 16384] f32 row-major, x: [16384,1], b: [16384,1]
// Inputs (metadata order): alpha[1], A, x, beta[1], b
// HBM-bound: stream A once with float4 loads, block-per-row reduction.

#define ROWS 16384
#define COLS 16384
#define TPB  256

__global__ __launch_bounds__(TPB) void gemv_kernel(
    const float* __restrict__ alpha,
    const float* __restrict__ A,
    const float* __restrict__ x,
    const float* __restrict__ beta,
    const float* __restrict__ b,
    float* __restrict__ y)
{
    const int row = blockIdx.x;
    const int tid = threadIdx.x;

    const float4* __restrict__ arow = reinterpret_cast<const float4*>(A + (size_t)row * COLS);
    const float4* __restrict__ xv   = reinterpret_cast<const float4*>(x);

    // COLS/4 = 4096 float4 per row; 256 threads -> 16 iterations each.
    float acc = 0.0f;
    #pragma unroll 4
    for (int i = tid; i < COLS / 4; i += TPB) {
        float4 a = __ldcs(&arow[i]);   // streaming: A is read exactly once
        float4 v = __ldg(&xv[i]);      // x is hot in L2/L1
        acc = fmaf(a.x, v.x, acc);
        acc = fmaf(a.y, v.y, acc);
        acc = fmaf(a.z, v.z, acc);
        acc = fmaf(a.w, v.w, acc);
    }

    // warp reduce
    #pragma unroll
    for (int off = 16; off > 0; off >>= 1)
        acc += __shfl_xor_sync(0xFFFFFFFFu, acc, off);

    __shared__ float warp_sums[TPB / 32];
    const int lane = tid & 31;
    const int wid  = tid >> 5;
    if (lane == 0) warp_sums[wid] = acc;
    __syncthreads();

    if (wid == 0) {
        float s = (lane < TPB / 32) ? warp_sums[lane] : 0.0f;
        #pragma unroll
        for (int off = 4; off > 0; off >>= 1)
            s += __shfl_xor_sync(0xFFFFFFFFu, s, off);
        if (lane == 0)
            y[row] = alpha[0] * s + beta[0] * b[row];
    }
}

extern "C" void kernel_launch(void* const* d_in, const int* in_sizes, int n_in,
                              void* d_out, int out_size) {
    const float* alpha = (const float*)d_in[0];
    const float* A     = (const float*)d_in[1];
    const float* x     = (const float*)d_in[2];
    const float* beta  = (const float*)d_in[3];
    const float* b     = (const float*)d_in[4];
    float* y = (float*)d_out;

    gemv_kernel<<<ROWS, TPB>>>(alpha, A, x, beta, b, y);
}